// round 15
// baseline (speedup 1.0000x reference)
#include <cuda_runtime.h>
#include <cstdint>

#define H 2048
#define S 8192
#define EB 256

// Dynamic smem layout (bytes) for k_energy
#define SU_OFF     0        // float4 sU[512]        (8192 B)
#define RING_OFF   8192     // 8 slots x 8192 B      (65536 B)
#define MBAR_OFF   73728    // 8 x uint64 mbarriers  (64 B)
#define SE_OFF     73792    // float sE[32]          (128 B)
#define SMZ_OFF    73920    // float sM, sInvZ       (8 B)
#define SMEM_TOTAL 73984

// Scratch (no allocs allowed). g_u starts zero (static init); k_energy
// re-zeros it each invocation after the grid barrier, so "g_u == 0 on entry"
// holds for the correctness run, the capture, and every graph replay.
__device__ float    g_u[H];
__device__ float    g_mb[EB];
__device__ float    g_zb[EB];
__device__ unsigned g_count = 0;   // barrier arrival counter (self-resetting)
__device__ unsigned g_gen   = 0;   // barrier generation (monotonic across replays)

// ---------------------------------------------------------------------------
// Kernel 1: u[j] += sum over a 16-row i-chunk of h[i] * W[i, j]
// Grid (H/256, 128) = 1024 blocks; fully unrolled. (Proven R9/R10.)
// ---------------------------------------------------------------------------
#define ICHUNKS 128
#define IROWS   (H / ICHUNKS)     // 16

__global__ void k_compute_u(const float* __restrict__ h,
                            const float* __restrict__ W) {
    const int j  = blockIdx.x * blockDim.x + threadIdx.x;
    const int i0 = blockIdx.y * IROWS;

    float acc = 0.0f;
#pragma unroll
    for (int r = 0; r < IROWS; ++r) {
        const int i = i0 + r;
        acc = fmaf(__ldg(h + i), W[(size_t)i * H + j], acc);
    }
    atomicAdd(&g_u[j], acc);
}

// ---------------------------------------------------------------------------
// Grid barrier across EB=256 blocks (all resident: 2/SM by 74KB smem,
// 148 SMs x 2 = 296 slots >= 256). Monotonic generation -> replay safe.
// ---------------------------------------------------------------------------
__device__ __forceinline__ void grid_barrier() {
    __syncthreads();
    __threadfence();
    if (threadIdx.x == 0) {
        unsigned gen0 = *(volatile unsigned*)&g_gen;
        if (atomicAdd(&g_count, 1u) == EB - 1) {
            g_count = 0;
            __threadfence();
            atomicAdd(&g_gen, 1u);         // release
        } else {
            while (*(volatile unsigned*)&g_gen == gen0) { }
        }
        __threadfence();                   // acquire
    }
    __syncthreads();
}

// ---------------------------------------------------------------------------
// PTX helpers: mbarrier + 1D bulk async copy (gmem -> smem::cta)
// ---------------------------------------------------------------------------
__device__ __forceinline__ uint32_t smem_u32(const void* p) {
    uint32_t a;
    asm("{ .reg .u64 t; cvta.to.shared.u64 t, %1; cvt.u32.u64 %0, t; }"
        : "=r"(a) : "l"(p));
    return a;
}
__device__ __forceinline__ void mbar_init(uint32_t addr, uint32_t cnt) {
    asm volatile("mbarrier.init.shared.b64 [%0], %1;"
                 :: "r"(addr), "r"(cnt) : "memory");
}
__device__ __forceinline__ void mbar_expect_tx(uint32_t addr, uint32_t bytes) {
    asm volatile("mbarrier.arrive.expect_tx.shared.b64 _, [%0], %1;"
                 :: "r"(addr), "r"(bytes) : "memory");
}
__device__ __forceinline__ void bulk_copy(uint32_t dst, const void* src,
                                          uint32_t bytes, uint32_t mbar) {
    asm volatile(
        "cp.async.bulk.shared::cta.global.mbarrier::complete_tx::bytes "
        "[%0], [%1], %2, [%3];"
        :: "r"(dst), "l"(src), "r"(bytes), "r"(mbar) : "memory");
}
__device__ __forceinline__ void mbar_wait(uint32_t addr, uint32_t parity) {
    asm volatile(
        "{\n\t.reg .pred P;\n\t"
        "WAIT_%=:\n\t"
        "mbarrier.try_wait.parity.acquire.cta.shared::cta.b64 P, [%0], %1, 0x989680;\n\t"
        "@P bra.uni DONE_%=;\n\t"
        "bra.uni WAIT_%=;\n\t"
        "DONE_%=:\n\t}"
        :: "r"(addr), "r"(parity) : "memory");
}

// ---------------------------------------------------------------------------
// Kernel 2: energies + softmax, TMA-fed.
// Phase A: warp w owns smem slot w (8KB) + mbarrier w; rows w, w+8, w+16,
// w+24 of this block's 32-row strip. Elected lane bulk-copies the next row
// into its slot right after the FMA chain has consumed the current one
// (depth-1 self-refilling pipeline; 8 copies in flight per block,
// continuous). u staged once in smem. Energies -> sE; block emits (m_b,z_b).
// Barrier. Phase B: redundant global (M, 1/Z) reduce per block; each block
// normalizes its own 32 energies. Blocks 0..7 re-zero g_u.
// ---------------------------------------------------------------------------
__global__ __launch_bounds__(256, 2)
void k_energy(const float* __restrict__ enc, float* __restrict__ out) {
    extern __shared__ __align__(16) char smem[];
    float4* sU  = reinterpret_cast<float4*>(smem + SU_OFF);
    float*  sE  = reinterpret_cast<float*>(smem + SE_OFF);
    float*  sMZ = reinterpret_cast<float*>(smem + SMZ_OFF);

    const int tid  = threadIdx.x;
    const int wid  = tid >> 5;         // 0..7
    const int lane = tid & 31;

    const uint32_t smem_base = smem_u32(smem);
    const uint32_t mbar      = smem_base + MBAR_OFF + wid * 8;
    const uint32_t slot      = smem_base + RING_OFF + wid * 8192;
    const float4*  slot4     =
        reinterpret_cast<const float4*>(smem + RING_OFF + wid * 8192);

    if (tid < 8) mbar_init(smem_base + MBAR_OFF + tid * 8, 1);
    __syncthreads();

    const int s_base = blockIdx.x * 32;

    // Prologue: start gen-0 copy for this warp's slot.
    if (lane == 0) {
        mbar_expect_tx(mbar, 8192);
        bulk_copy(slot, enc + (size_t)(s_base + wid) * H, 8192, mbar);
    }

    // Stage u into smem while copies are in flight (L2-hot after k_compute_u).
    {
        const float4* uv = reinterpret_cast<const float4*>(g_u);
        sU[tid]       = uv[tid];
        sU[tid + 256] = uv[tid + 256];
    }
    __syncthreads();

    for (int g = 0; g < 4; ++g) {
        mbar_wait(mbar, g & 1);        // gen g data landed (acquire)

        float acc = 0.0f;
#pragma unroll
        for (int k = 0; k < 16; ++k) {
            float4 v = slot4[lane + 32 * k];
            float4 u = sU  [lane + 32 * k];
            acc = fmaf(v.x, u.x, acc);
            acc = fmaf(v.y, u.y, acc);
            acc = fmaf(v.z, u.z, acc);
            acc = fmaf(v.w, u.w, acc);
        }
        // FMA chain has consumed every LDS of this slot -> safe to refill.
        // (DMA write lands >=100s of cycles after issue; LDS completed ~29.)
        if (g < 3 && lane == 0) {
            mbar_expect_tx(mbar, 8192);
            bulk_copy(slot, enc + (size_t)(s_base + wid + 8 * (g + 1)) * H,
                      8192, mbar);
        }
#pragma unroll
        for (int off = 16; off; off >>= 1)
            acc += __shfl_xor_sync(0xFFFFFFFFu, acc, off);
        if (lane == 0) sE[wid + 8 * g] = acc;
    }
    __syncthreads();

    // Block-local (m, z) over this block's 32 energies (warp 0).
    if (wid == 0) {
        float e = sE[lane];
        float m = e;
#pragma unroll
        for (int off = 16; off; off >>= 1)
            m = fmaxf(m, __shfl_xor_sync(0xFFFFFFFFu, m, off));
        float z = __expf(e - m);
#pragma unroll
        for (int off = 16; off; off >>= 1)
            z += __shfl_xor_sync(0xFFFFFFFFu, z, off);
        if (lane == 0) { g_mb[blockIdx.x] = m; g_zb[blockIdx.x] = z; }
    }

    grid_barrier();   // all (m_b, z_b) visible; all g_u reads complete

    // ---- Phase B: global (M, 1/Z), redundant per block ----
    if (tid < 32) {
        float m = -1e30f;
#pragma unroll
        for (int i = 0; i < EB / 32; ++i)
            m = fmaxf(m, g_mb[lane + i * 32]);
#pragma unroll
        for (int off = 16; off; off >>= 1)
            m = fmaxf(m, __shfl_xor_sync(0xFFFFFFFFu, m, off));
        float z = 0.0f;
#pragma unroll
        for (int i = 0; i < EB / 32; ++i)
            z += g_zb[lane + i * 32] * __expf(g_mb[lane + i * 32] - m);
#pragma unroll
        for (int off = 16; off; off >>= 1)
            z += __shfl_xor_sync(0xFFFFFFFFu, z, off);
        if (lane == 0) { sMZ[0] = m; sMZ[1] = 1.0f / z; }
    }
    __syncthreads();

    // Normalize this block's 32 energies (still in smem) -> out.
    if (tid < 32)
        out[blockIdx.x * 32 + tid] = __expf(sE[tid] - sMZ[0]) * sMZ[1];

    // Restore g_u == 0 invariant (u consumed before the barrier).
    if (blockIdx.x < 8)
        g_u[blockIdx.x * 256 + tid] = 0.0f;
}

// ---------------------------------------------------------------------------
// Launch. Inputs: hidden[2048], encoder_outputs[8192*2048], W[2048*2048],
// b[2048] (zero + softmax-invariant -> ignored). Output: 8192 floats.
// ---------------------------------------------------------------------------
extern "C" void kernel_launch(void* const* d_in, const int* in_sizes, int n_in,
                              void* d_out, int out_size) {
    const float* hidden = (const float*)d_in[0];
    const float* enc    = (const float*)d_in[1];
    const float* W      = (const float*)d_in[2];
    float* out          = (float*)d_out;

    cudaFuncSetAttribute(k_energy, cudaFuncAttributeMaxDynamicSharedMemorySize,
                         SMEM_TOTAL);

    dim3 g1(H / 256, ICHUNKS);   // (8, 128) = 1024 blocks
    k_compute_u<<<g1, 256>>>(hidden, W);

    k_energy<<<EB, 256, SMEM_TOTAL>>>(enc, out);
}

// round 16
// speedup vs baseline: 1.0977x; 1.0977x over previous
#include <cuda_runtime.h>
#include <cstdint>

#define H 2048
#define S 8192
#define EB 128               // 1 block/SM (smem-forced) -> all resident

// Dynamic smem layout (bytes) for k_energy
#define RING_OFF   0         // 16 slots x 8192 B  (warp w -> slots 2w, 2w+1)
#define MBAR_OFF   131072    // 16 x uint64 mbarriers
#define SE_OFF     131200    // float sE[64]
#define SMZ_OFF    131456    // float sM, sInvZ
#define SMEM_TOTAL 131520

// Scratch (no allocs allowed). g_u starts zero (static init); k_energy
// re-zeros it each invocation after the grid barrier.
__device__ float    g_u[H];
__device__ float    g_mb[EB];
__device__ float    g_zb[EB];
__device__ unsigned g_count = 0;
__device__ unsigned g_gen   = 0;

// ---------------------------------------------------------------------------
// Kernel 1: u GEMV. Grid (8,128)=1024 blocks, 16 fully unrolled rows/thread.
// (Proven R9/R10.)
// ---------------------------------------------------------------------------
#define ICHUNKS 128
#define IROWS   (H / ICHUNKS)     // 16

__global__ void k_compute_u(const float* __restrict__ h,
                            const float* __restrict__ W) {
    const int j  = blockIdx.x * blockDim.x + threadIdx.x;
    const int i0 = blockIdx.y * IROWS;

    float acc = 0.0f;
#pragma unroll
    for (int r = 0; r < IROWS; ++r) {
        const int i = i0 + r;
        acc = fmaf(__ldg(h + i), W[(size_t)i * H + j], acc);
    }
    atomicAdd(&g_u[j], acc);
}

// Grid barrier across EB=128 blocks (all resident: 1/SM by smem, 128 <= 148).
__device__ __forceinline__ void grid_barrier() {
    __syncthreads();
    __threadfence();
    if (threadIdx.x == 0) {
        unsigned gen0 = *(volatile unsigned*)&g_gen;
        if (atomicAdd(&g_count, 1u) == EB - 1) {
            g_count = 0;
            __threadfence();
            atomicAdd(&g_gen, 1u);         // release
        } else {
            while (*(volatile unsigned*)&g_gen == gen0) { }
        }
        __threadfence();                   // acquire
    }
    __syncthreads();
}

// ---- PTX helpers: mbarrier + 1D bulk async copy (gmem -> smem::cta) ----
__device__ __forceinline__ uint32_t smem_u32(const void* p) {
    uint32_t a;
    asm("{ .reg .u64 t; cvta.to.shared.u64 t, %1; cvt.u32.u64 %0, t; }"
        : "=r"(a) : "l"(p));
    return a;
}
__device__ __forceinline__ void mbar_init(uint32_t addr, uint32_t cnt) {
    asm volatile("mbarrier.init.shared.b64 [%0], %1;"
                 :: "r"(addr), "r"(cnt) : "memory");
}
__device__ __forceinline__ void mbar_expect_tx(uint32_t addr, uint32_t bytes) {
    asm volatile("mbarrier.arrive.expect_tx.shared.b64 _, [%0], %1;"
                 :: "r"(addr), "r"(bytes) : "memory");
}
__device__ __forceinline__ void bulk_copy(uint32_t dst, const void* src,
                                          uint32_t bytes, uint32_t mbar) {
    asm volatile(
        "cp.async.bulk.shared::cta.global.mbarrier::complete_tx::bytes "
        "[%0], [%1], %2, [%3];"
        :: "r"(dst), "l"(src), "r"(bytes), "r"(mbar) : "memory");
}
__device__ __forceinline__ void mbar_wait(uint32_t addr, uint32_t parity) {
    asm volatile(
        "{\n\t.reg .pred P;\n\t"
        "WAIT_%=:\n\t"
        "mbarrier.try_wait.parity.acquire.cta.shared::cta.b64 P, [%0], %1, 0x989680;\n\t"
        "@P bra.uni DONE_%=;\n\t"
        "bra.uni WAIT_%=;\n\t"
        "DONE_%=:\n\t}"
        :: "r"(addr), "r"(parity) : "memory");
}

// ---------------------------------------------------------------------------
// Kernel 2: energies + softmax, DOUBLE-BUFFERED TMA.
// 128 blocks x 256 thr, 1 block/SM. Block b owns rows [64b, 64b+64); warp w
// owns rows 64b + 8w .. +8, two 8KB slots + two mbarriers. Copies for rows
// g and g+1 are in flight while row g computes; refill g+2 after consume.
// TMA stream continuous (16 copies in flight per SM). u register-resident
// (8 warps/SM -> no reg pressure). Barrier. Phase B: redundant (M,1/Z) over
// 128 pairs; each block normalizes its 64 energies. Blocks 0..7 re-zero g_u.
// ---------------------------------------------------------------------------
__global__ __launch_bounds__(256, 1)
void k_energy(const float* __restrict__ enc, float* __restrict__ out) {
    extern __shared__ __align__(16) char smem[];
    float*  sE  = reinterpret_cast<float*>(smem + SE_OFF);
    float*  sMZ = reinterpret_cast<float*>(smem + SMZ_OFF);

    const int tid  = threadIdx.x;
    const int wid  = tid >> 5;         // 0..7
    const int lane = tid & 31;

    const uint32_t smem_base = smem_u32(smem);
    const uint32_t mbar0 = smem_base + MBAR_OFF + (wid * 2    ) * 8;
    const uint32_t mbar1 = smem_base + MBAR_OFF + (wid * 2 + 1) * 8;
    const uint32_t slot0 = smem_base + RING_OFF + (wid * 2    ) * 8192;
    const uint32_t slot1 = smem_base + RING_OFF + (wid * 2 + 1) * 8192;
    const float4* s4_0 = reinterpret_cast<const float4*>(smem + RING_OFF + (wid * 2    ) * 8192);
    const float4* s4_1 = reinterpret_cast<const float4*>(smem + RING_OFF + (wid * 2 + 1) * 8192);

    if (tid < 16) mbar_init(smem_base + MBAR_OFF + tid * 8, 1);
    __syncthreads();

    const int r0 = blockIdx.x * 64 + wid * 8;   // this warp's first row

    // Prologue: launch copies for rows r0 and r0+1.
    if (lane == 0) {
        mbar_expect_tx(mbar0, 8192);
        bulk_copy(slot0, enc + (size_t)r0 * H, 8192, mbar0);
        mbar_expect_tx(mbar1, 8192);
        bulk_copy(slot1, enc + (size_t)(r0 + 1) * H, 8192, mbar1);
    }

    // u register-resident (L2-hot after k_compute_u).
    const float4* uv = reinterpret_cast<const float4*>(g_u);
    float4 u[16];
#pragma unroll
    for (int k = 0; k < 16; ++k)
        u[k] = uv[lane + k * 32];

#pragma unroll
    for (int g = 0; g < 8; ++g) {
        const uint32_t mb   = (g & 1) ? mbar1 : mbar0;
        const float4*  s4   = (g & 1) ? s4_1  : s4_0;
        const uint32_t slot = (g & 1) ? slot1 : slot0;

        mbar_wait(mb, (g >> 1) & 1);   // this buffer's g-th use parity

        float acc = 0.0f;
#pragma unroll
        for (int k = 0; k < 16; ++k) {
            float4 v = s4[lane + 32 * k];
            acc = fmaf(v.x, u[k].x, acc);
            acc = fmaf(v.y, u[k].y, acc);
            acc = fmaf(v.z, u[k].z, acc);
            acc = fmaf(v.w, u[k].w, acc);
        }
#pragma unroll
        for (int off = 16; off; off >>= 1)
            acc += __shfl_xor_sync(0xFFFFFFFFu, acc, off);
        if (lane == 0) {
            sE[wid * 8 + g] = acc;
            // Refill this buffer for row g+2 (all LDS of this slot are
            // retired: their values fed acc, which the shuffle consumed).
            if (g < 6) {
                mbar_expect_tx(mb, 8192);
                bulk_copy(slot, enc + (size_t)(r0 + g + 2) * H, 8192, mb);
            }
        }
    }
    __syncthreads();

    // Block-local (m, z) over this block's 64 energies (warp 0).
    if (wid == 0) {
        float e0 = sE[lane];
        float e1 = sE[lane + 32];
        float m = fmaxf(e0, e1);
#pragma unroll
        for (int off = 16; off; off >>= 1)
            m = fmaxf(m, __shfl_xor_sync(0xFFFFFFFFu, m, off));
        float z = __expf(e0 - m) + __expf(e1 - m);
#pragma unroll
        for (int off = 16; off; off >>= 1)
            z += __shfl_xor_sync(0xFFFFFFFFu, z, off);
        if (lane == 0) { g_mb[blockIdx.x] = m; g_zb[blockIdx.x] = z; }
    }

    grid_barrier();   // all (m_b, z_b) visible; all g_u reads complete

    // ---- Phase B: global (M, 1/Z), redundant per block ----
    if (tid < 32) {
        float m = -1e30f;
#pragma unroll
        for (int i = 0; i < EB / 32; ++i)
            m = fmaxf(m, g_mb[lane + i * 32]);
#pragma unroll
        for (int off = 16; off; off >>= 1)
            m = fmaxf(m, __shfl_xor_sync(0xFFFFFFFFu, m, off));
        float z = 0.0f;
#pragma unroll
        for (int i = 0; i < EB / 32; ++i)
            z += g_zb[lane + i * 32] * __expf(g_mb[lane + i * 32] - m);
#pragma unroll
        for (int off = 16; off; off >>= 1)
            z += __shfl_xor_sync(0xFFFFFFFFu, z, off);
        if (lane == 0) { sMZ[0] = m; sMZ[1] = 1.0f / z; }
    }
    __syncthreads();

    // Normalize this block's 64 energies -> out.
    if (tid < 64)
        out[blockIdx.x * 64 + tid] = __expf(sE[tid] - sMZ[0]) * sMZ[1];

    // Restore g_u == 0 invariant (u consumed before the barrier).
    if (blockIdx.x < 8)
        g_u[blockIdx.x * 256 + tid] = 0.0f;
}

// ---------------------------------------------------------------------------
// Launch. Inputs: hidden[2048], encoder_outputs[8192*2048], W[2048*2048],
// b[2048] (zero + softmax-invariant -> ignored). Output: 8192 floats.
// ---------------------------------------------------------------------------
extern "C" void kernel_launch(void* const* d_in, const int* in_sizes, int n_in,
                              void* d_out, int out_size) {
    const float* hidden = (const float*)d_in[0];
    const float* enc    = (const float*)d_in[1];
    const float* W      = (const float*)d_in[2];
    float* out          = (float*)d_out;

    cudaFuncSetAttribute(k_energy, cudaFuncAttributeMaxDynamicSharedMemorySize,
                         SMEM_TOTAL);

    dim3 g1(H / 256, ICHUNKS);   // (8, 128) = 1024 blocks
    k_compute_u<<<g1, 256>>>(hidden, W);

    k_energy<<<EB, 256, SMEM_TOTAL>>>(enc, out);
}

// round 17
// speedup vs baseline: 1.1379x; 1.0366x over previous
#include <cuda_runtime.h>

#define H 2048
#define S 8192
#define EB 256               // k_energy blocks (all resident: 2/SM, 128 regs)

// Scratch (no allocs allowed). g_u starts zero (static init); k_energy
// re-zeros it each invocation after the grid barrier, so "g_u == 0 on entry"
// holds for the correctness run, the capture, and every graph replay.
__device__ float    g_u[H];
__device__ float    g_mb[EB];
__device__ float    g_zb[EB];
__device__ unsigned g_count = 0;   // barrier arrival counter (self-resetting)
__device__ unsigned g_gen   = 0;   // barrier generation (monotonic across replays)

// ---------------------------------------------------------------------------
// Kernel 1: u[j] += sum over a 16-row i-chunk of h[i] * W[i, j]
// Grid (H/256, 128) = 1024 blocks; 16 fully unrolled rows/thread (proven R9).
// Signals PDL dependents after its partial is committed.
// ---------------------------------------------------------------------------
#define ICHUNKS 128
#define IROWS   (H / ICHUNKS)     // 16

__global__ void k_compute_u(const float* __restrict__ h,
                            const float* __restrict__ W) {
    const int j  = blockIdx.x * blockDim.x + threadIdx.x;
    const int i0 = blockIdx.y * IROWS;

    float acc = 0.0f;
#pragma unroll
    for (int r = 0; r < IROWS; ++r) {
        const int i = i0 + r;
        acc = fmaf(__ldg(h + i), W[(size_t)i * H + j], acc);
    }
    atomicAdd(&g_u[j], acc);

    // PDL: this block's writes are done; dependents may begin launching.
    asm volatile("griddepcontrol.launch_dependents;" ::: "memory");
}

// ---------------------------------------------------------------------------
// Grid barrier across EB=256 blocks (all resident; geometry proven R10).
// Monotonic generation counter -> graph-replay safe.
// ---------------------------------------------------------------------------
__device__ __forceinline__ void grid_barrier() {
    __syncthreads();
    __threadfence();
    if (threadIdx.x == 0) {
        unsigned gen0 = *(volatile unsigned*)&g_gen;
        if (atomicAdd(&g_count, 1u) == EB - 1) {
            g_count = 0;
            __threadfence();
            atomicAdd(&g_gen, 1u);         // release
        } else {
            while (*(volatile unsigned*)&g_gen == gen0) { }
        }
        __threadfence();                   // acquire
    }
    __syncthreads();
}

// ---------------------------------------------------------------------------
// Kernel 2: energies + softmax (R10-proven body), PDL-launched.
// griddepcontrol.wait right before consuming g_u: the launch/ramp overlaps
// k_compute_u's tail. Phase A: u register-resident per warp (64 regs); each
// warp streams 4 enc rows (16 independent LDG.128/row); energies -> smem;
// block emits (m_b, z_b). Barrier. Phase B: every block redundantly reduces
// the 256 (m,z) pairs to (M, 1/Z) and normalizes its OWN 32 energies from
// smem. Blocks 0..7 re-zero g_u.
// ---------------------------------------------------------------------------
#define RPW 4

__global__ __launch_bounds__(256, 2)
void k_energy(const float* __restrict__ enc, float* __restrict__ out) {
    __shared__ float sE[32];           // 8 warps * 4 rows
    __shared__ float sM, sInvZ;

    const int tid  = threadIdx.x;
    const int wid  = tid >> 5;         // 0..7
    const int lane = tid & 31;
    const int s0   = (blockIdx.x * 8 + wid) * RPW;

    // Wait for ALL k_compute_u blocks (no-op if not PDL-launched).
    asm volatile("griddepcontrol.wait;" ::: "memory");

    // ---- Phase A: cache u in registers (L2-hot after k_compute_u) ----
    const float4* uv = reinterpret_cast<const float4*>(g_u);
    float4 u[16];
#pragma unroll
    for (int k = 0; k < 16; ++k)
        u[k] = uv[lane + k * 32];

#pragma unroll
    for (int r = 0; r < RPW; ++r) {
        const float4* row =
            reinterpret_cast<const float4*>(enc + (size_t)(s0 + r) * H);
        float acc = 0.0f;
#pragma unroll
        for (int k = 0; k < 16; ++k) {
            float4 v = row[lane + k * 32];
            acc = fmaf(v.x, u[k].x, acc);
            acc = fmaf(v.y, u[k].y, acc);
            acc = fmaf(v.z, u[k].z, acc);
            acc = fmaf(v.w, u[k].w, acc);
        }
#pragma unroll
        for (int off = 16; off; off >>= 1)
            acc += __shfl_xor_sync(0xFFFFFFFFu, acc, off);
        if (lane == 0) sE[wid * RPW + r] = acc;
    }
    __syncthreads();

    // Block-local (m, z) over this block's 32 energies (warp 0).
    if (wid == 0) {
        float e = sE[lane];
        float m = e;
#pragma unroll
        for (int off = 16; off; off >>= 1)
            m = fmaxf(m, __shfl_xor_sync(0xFFFFFFFFu, m, off));
        float z = __expf(e - m);
#pragma unroll
        for (int off = 16; off; off >>= 1)
            z += __shfl_xor_sync(0xFFFFFFFFu, z, off);
        if (lane == 0) { g_mb[blockIdx.x] = m; g_zb[blockIdx.x] = z; }
    }

    grid_barrier();   // all (m_b, z_b) visible; all g_u reads complete

    // ---- Phase B: global (M, 1/Z), redundant per block ----
    if (tid < 32) {
        float m = -1e30f;
#pragma unroll
        for (int i = 0; i < EB / 32; ++i)
            m = fmaxf(m, g_mb[lane + i * 32]);
#pragma unroll
        for (int off = 16; off; off >>= 1)
            m = fmaxf(m, __shfl_xor_sync(0xFFFFFFFFu, m, off));
        float z = 0.0f;
#pragma unroll
        for (int i = 0; i < EB / 32; ++i)
            z += g_zb[lane + i * 32] * __expf(g_mb[lane + i * 32] - m);
#pragma unroll
        for (int off = 16; off; off >>= 1)
            z += __shfl_xor_sync(0xFFFFFFFFu, z, off);
        if (lane == 0) { sM = m; sInvZ = 1.0f / z; }
    }
    __syncthreads();

    // Normalize this block's 32 energies (still in smem) -> out.
    if (tid < 32)
        out[blockIdx.x * 32 + tid] = __expf(sE[tid] - sM) * sInvZ;

    // Restore g_u == 0 invariant (u consumed before the barrier).
    if (blockIdx.x < 8)
        g_u[blockIdx.x * 256 + tid] = 0.0f;
}

// ---------------------------------------------------------------------------
// Launch. Inputs: hidden[2048], encoder_outputs[8192*2048], W[2048*2048],
// b[2048] (zero + softmax-invariant -> ignored). Output: 8192 floats.
// k_energy is launched with Programmatic Stream Serialization so its
// launch/ramp overlaps k_compute_u's tail wave.
// ---------------------------------------------------------------------------
extern "C" void kernel_launch(void* const* d_in, const int* in_sizes, int n_in,
                              void* d_out, int out_size) {
    const float* hidden = (const float*)d_in[0];
    const float* enc    = (const float*)d_in[1];
    const float* W      = (const float*)d_in[2];
    float* out          = (float*)d_out;

    dim3 g1(H / 256, ICHUNKS);   // (8, 128) = 1024 blocks
    k_compute_u<<<g1, 256>>>(hidden, W);

    cudaLaunchConfig_t cfg = {};
    cfg.gridDim  = dim3(EB, 1, 1);
    cfg.blockDim = dim3(256, 1, 1);
    cfg.dynamicSmemBytes = 0;
    cudaLaunchAttribute attr[1];
    attr[0].id = cudaLaunchAttributeProgrammaticStreamSerialization;
    attr[0].val.programmaticStreamSerializationAllowed = 1;
    cfg.attrs    = attr;
    cfg.numAttrs = 1;
    cudaLaunchKernelEx(&cfg, k_energy, enc, out);
}